// round 6
// baseline (speedup 1.0000x reference)
#include <cuda_runtime.h>
#include <math.h>

#define NB 592          // blocks
#define NT 256          // threads per block
#define NWARP 8
#define F 128           // O_DIM = T_DIM = OUT_F
#define LOG2E 1.4426950408889634f

// Scratch (__device__ globals; zero-initialized at module load)
__device__ __align__(16) float g_u[F];        // W_j_w^T @ w_r
__device__ float g_const;                     // w_l.z_i + w_r.b_j
__device__ int   g_flag;                      // prep-done flag
__device__ int   g_count;                     // finished-block counter
__device__ float g_bm[NB];
__device__ float g_bl[NB];
__device__ __align__(16) float g_bacc[NB][F];

__device__ __forceinline__ float warp_red_sum(float v) {
    v += __shfl_xor_sync(0xffffffffu, v, 16);
    v += __shfl_xor_sync(0xffffffffu, v, 8);
    v += __shfl_xor_sync(0xffffffffu, v, 4);
    v += __shfl_xor_sync(0xffffffffu, v, 2);
    v += __shfl_xor_sync(0xffffffffu, v, 1);
    return v;
}
__device__ __forceinline__ float warp_red_max(float v) {
    v = fmaxf(v, __shfl_xor_sync(0xffffffffu, v, 16));
    v = fmaxf(v, __shfl_xor_sync(0xffffffffu, v, 8));
    v = fmaxf(v, __shfl_xor_sync(0xffffffffu, v, 4));
    v = fmaxf(v, __shfl_xor_sync(0xffffffffu, v, 2));
    v = fmaxf(v, __shfl_xor_sync(0xffffffffu, v, 1));
    return v;
}
__device__ __forceinline__ float fexp2(float x) {
    float r;
    asm("ex2.approx.ftz.f32 %0, %1;" : "=f"(r) : "f"(x));
    return r;
}

__global__ __launch_bounds__(NT)
void fused_kernel(const float* __restrict__ h_j, int n,
                  const float* __restrict__ h_i,
                  const float* __restrict__ W_i_w,
                  const float* __restrict__ W_i_b,
                  const float* __restrict__ W_j_w,
                  const float* __restrict__ W_j_b,
                  const float* __restrict__ W_ij,
                  float* __restrict__ out) {
    const int t    = threadIdx.x;
    const int lane = t & 31;
    const int w    = t >> 5;
    const int sub  = lane & 7;   // 8-lane feature group
    const int g    = lane >> 3;  // row-within-4 selector

    __shared__ __align__(16) float s_hi[F];
    __shared__ __align__(16) float s_wr[F];
    __shared__ __align__(16) float s_z[F];
    __shared__ __align__(16) float s_u[2][F];
    __shared__ __align__(16) float sacc[NWARP][F];
    __shared__ float sm[NWARP], sl[NWARP];
    __shared__ __align__(16) float sv[F];
    __shared__ float sLred[NWARP];
    __shared__ float s_red[NWARP];
    __shared__ float sM;
    __shared__ int   amLast;

    // ======================= PHASE 0: prep (block 0) ========================
    if (blockIdx.x == 0) {
        if (t < F) { s_hi[t] = h_i[t]; s_wr[t] = W_ij[F + t]; }
        __syncthreads();

        // z_i: warp w computes rows w*16 .. w*16+15, 4 rows per pass
        #pragma unroll
        for (int pass = 0; pass < 4; pass++) {
            const int f = w * 16 + pass * 4 + g;
            float p = 0.f;
            #pragma unroll
            for (int q = 0; q < 4; q++) {
                const float4 a = *reinterpret_cast<const float4*>(&W_i_w[f * F + (q * 8 + sub) * 4]);
                const float4 b = *reinterpret_cast<const float4*>(&s_hi[(q * 8 + sub) * 4]);
                p += a.x * b.x + a.y * b.y + a.z * b.z + a.w * b.w;
            }
            p += __shfl_xor_sync(0xffffffffu, p, 4);
            p += __shfl_xor_sync(0xffffffffu, p, 2);
            p += __shfl_xor_sync(0xffffffffu, p, 1);
            if (sub == 0) s_z[f] = p + W_i_b[f];
        }
        // u[col] = sum_f wr[f] * W_j_w[f,col]; 2-way f split
        {
            const int col = t & 127, half = t >> 7;
            float u = 0.f;
            #pragma unroll 8
            for (int ff = 0; ff < 64; ff++) {
                const int f = half * 64 + ff;
                u += s_wr[f] * W_j_w[f * F + col];
            }
            s_u[half][col] = u;
        }
        __syncthreads();
        if (t < F) g_u[t] = s_u[0][t] + s_u[1][t];
        if (w == 0) {
            float acc = 0.f;
            #pragma unroll
            for (int f = lane; f < F; f += 32)
                acc += W_ij[f] * s_z[f] + s_wr[f] * W_j_b[f];
            acc = warp_red_sum(acc);
            if (lane == 0) g_const = acc;
        }
        __syncthreads();
        __threadfence();
        if (t == 0)
            asm volatile("st.global.release.gpu.b32 [%0], %1;" :: "l"(&g_flag), "r"(1) : "memory");
    } else {
        if (t == 0) {
            int f;
            while (true) {
                asm volatile("ld.global.acquire.gpu.b32 %0, [%1];" : "=r"(f) : "l"(&g_flag) : "memory");
                if (f) break;
                __nanosleep(64);
            }
        }
        __syncthreads();
    }

    // ======================= PHASE 1: streaming =============================
    float4 uu[4];
    #pragma unroll
    for (int q = 0; q < 4; q++)
        uu[q] = *reinterpret_cast<const float4*>(&g_u[(q * 8 + sub) * 4]);
    const float c = g_const;

    float m = -1e30f, l = 0.f;
    float4 acc[4];
    #pragma unroll
    for (int q = 0; q < 4; q++) acc[q] = make_float4(0.f, 0.f, 0.f, 0.f);

    const int nchunks = (n + 3) >> 2;
    const int NW  = NB * NWARP;
    const int per = (nchunks + NW - 1) / NW;
    const int W   = blockIdx.x * NWARP + w;
    int ch        = W * per;
    const int chEnd = min(ch + per, nchunks);

    const float4* __restrict__ hj4 = reinterpret_cast<const float4*>(h_j);

    float4 x[4];
    bool have = ch < chEnd;
    if (have) {
        const size_t rb = (size_t)min(ch * 4 + g, n - 1) * 32;
        #pragma unroll
        for (int q = 0; q < 4; q++) x[q] = __ldcs(&hj4[rb + q * 8 + sub]);
    }
    while (have) {
        const int nx  = ch + 1;
        const bool hn = nx < chEnd;
        float4 xn[4];
        if (hn) {
            const size_t rb = (size_t)min(nx * 4 + g, n - 1) * 32;
            #pragma unroll
            for (int q = 0; q < 4; q++) xn[q] = __ldcs(&hj4[rb + q * 8 + sub]);
        }

        float p = 0.f;
        #pragma unroll
        for (int q = 0; q < 4; q++)
            p += x[q].x * uu[q].x + x[q].y * uu[q].y + x[q].z * uu[q].z + x[q].w * uu[q].w;
        p += __shfl_xor_sync(0xffffffffu, p, 4);
        p += __shfl_xor_sync(0xffffffffu, p, 2);
        p += __shfl_xor_sync(0xffffffffu, p, 1);

        const float s = p + c;
        float e = (s > 0.f) ? s : 0.1f * s;
        if (ch * 4 + g >= n) e = -1e30f;

        const float mn    = fmaxf(m, e);
        const float scale = fexp2((m - mn) * LOG2E);
        const float wgt   = fexp2((e - mn) * LOG2E);
        l = l * scale + wgt;
        #pragma unroll
        for (int q = 0; q < 4; q++) {
            acc[q].x = acc[q].x * scale + wgt * x[q].x;
            acc[q].y = acc[q].y * scale + wgt * x[q].y;
            acc[q].z = acc[q].z * scale + wgt * x[q].z;
            acc[q].w = acc[q].w * scale + wgt * x[q].w;
        }
        m = mn;

        if (hn) {
            #pragma unroll
            for (int q = 0; q < 4; q++) x[q] = xn[q];
        }
        ch = nx; have = hn;
    }

    // merge 4 groups within warp (xor 8, 16)
    float M = m;
    M = fmaxf(M, __shfl_xor_sync(0xffffffffu, M, 8));
    M = fmaxf(M, __shfl_xor_sync(0xffffffffu, M, 16));
    const float sc = fexp2((m - M) * LOG2E);
    float L = l * sc;
    L += __shfl_xor_sync(0xffffffffu, L, 8);
    L += __shfl_xor_sync(0xffffffffu, L, 16);
    #pragma unroll
    for (int q = 0; q < 4; q++) {
        float a;
        a = acc[q].x * sc; a += __shfl_xor_sync(0xffffffffu, a, 8); a += __shfl_xor_sync(0xffffffffu, a, 16); acc[q].x = a;
        a = acc[q].y * sc; a += __shfl_xor_sync(0xffffffffu, a, 8); a += __shfl_xor_sync(0xffffffffu, a, 16); acc[q].y = a;
        a = acc[q].z * sc; a += __shfl_xor_sync(0xffffffffu, a, 8); a += __shfl_xor_sync(0xffffffffu, a, 16); acc[q].z = a;
        a = acc[q].w * sc; a += __shfl_xor_sync(0xffffffffu, a, 8); a += __shfl_xor_sync(0xffffffffu, a, 16); acc[q].w = a;
    }

    // merge warps within block
    if (g == 0) {
        #pragma unroll
        for (int q = 0; q < 4; q++)
            *reinterpret_cast<float4*>(&sacc[w][(q * 8 + sub) * 4]) = acc[q];
        if (sub == 0) { sm[w] = M; sl[w] = L; }
    }
    __syncthreads();

    if (t < F) {
        float BM = -1e30f;
        #pragma unroll
        for (int i = 0; i < NWARP; i++) BM = fmaxf(BM, sm[i]);
        float BL = 0.f, BA = 0.f;
        #pragma unroll
        for (int i = 0; i < NWARP; i++) {
            const float ws = fexp2((sm[i] - BM) * LOG2E);
            BL += ws * sl[i];
            BA += ws * sacc[i][t];
        }
        g_bacc[blockIdx.x][t] = BA;
        if (t == 0) { g_bm[blockIdx.x] = BM; g_bl[blockIdx.x] = BL; }
    }

    // ======================= PHASE 2: last-block finish =====================
    __threadfence();
    __syncthreads();
    if (t == 0) amLast = (atomicAdd(&g_count, 1) == NB - 1);
    __syncthreads();
    if (!amLast) return;

    // global max
    float lm = -1e30f;
    for (int b = t; b < NB; b += NT) lm = fmaxf(lm, g_bm[b]);
    lm = warp_red_max(lm);
    if (lane == 0) s_red[w] = lm;
    __syncthreads();
    if (t == 0) {
        float Mv = -1e30f;
        #pragma unroll
        for (int i = 0; i < NWARP; i++) Mv = fmaxf(Mv, s_red[i]);
        sM = Mv;
    }
    __syncthreads();
    const float GM = sM;

    // warp w combines blocks w, w+8, ...; lane holds cols lane*4..+3
    {
        float4 A = make_float4(0.f, 0.f, 0.f, 0.f);
        float Lw = 0.f;
        for (int b = w; b < NB; b += NWARP) {
            const float scb = fexp2((g_bm[b] - GM) * LOG2E);
            Lw += scb * g_bl[b];
            const float4 v = *reinterpret_cast<const float4*>(&g_bacc[b][lane * 4]);
            A.x += scb * v.x; A.y += scb * v.y; A.z += scb * v.z; A.w += scb * v.w;
        }
        *reinterpret_cast<float4*>(&sacc[w][lane * 4]) = A;
        if (lane == 0) sLred[w] = Lw;
    }
    __syncthreads();
    if (t < F) {
        float A = 0.f, Ltot = 0.f;
        #pragma unroll
        for (int i = 0; i < NWARP; i++) { A += sacc[i][t]; Ltot += sLred[i]; }
        sv[t] = A / Ltot;
    }
    __syncthreads();

    // matvec: warp w rows w*16..w*16+15, 4 rows per pass
    #pragma unroll
    for (int pass = 0; pass < 4; pass++) {
        const int k = w * 16 + pass * 4 + g;
        float p = 0.f;
        #pragma unroll
        for (int q = 0; q < 4; q++) {
            const float4 a = *reinterpret_cast<const float4*>(&W_j_w[k * F + (q * 8 + sub) * 4]);
            const float4 b = *reinterpret_cast<const float4*>(&sv[(q * 8 + sub) * 4]);
            p += a.x * b.x + a.y * b.y + a.z * b.z + a.w * b.w;
        }
        p += __shfl_xor_sync(0xffffffffu, p, 4);
        p += __shfl_xor_sync(0xffffffffu, p, 2);
        p += __shfl_xor_sync(0xffffffffu, p, 1);
        if (sub == 0) {
            const float h = p + W_j_b[k];
            out[k] = (h > 0.f) ? h : expm1f(h);
        }
    }

    // reset for next graph replay
    __syncthreads();
    if (t == 0) { g_count = 0; g_flag = 0; }
}

// inputs: 0:h_i 1:h_j 2:W_i_w 3:W_i_b 4:W_j_w 5:W_j_b 6:W_ij
extern "C" void kernel_launch(void* const* d_in, const int* in_sizes, int n_in,
                              void* d_out, int out_size) {
    const float* h_i   = (const float*)d_in[0];
    const float* h_j   = (const float*)d_in[1];
    const float* W_i_w = (const float*)d_in[2];
    const float* W_i_b = (const float*)d_in[3];
    const float* W_j_w = (const float*)d_in[4];
    const float* W_j_b = (const float*)d_in[5];
    const float* W_ij  = (const float*)d_in[6];
    float* out = (float*)d_out;

    const int n = in_sizes[1] / F;

    fused_kernel<<<NB, NT>>>(h_j, n, h_i, W_i_w, W_i_b, W_j_w, W_j_b, W_ij, out);
}